// round 7
// baseline (speedup 1.0000x reference)
#include <cuda_runtime.h>
#include <cuda_bf16.h>

// RecNN DAG evaluation. Key insight: the reference returns only
//   outputs[N-1] * w_final + b_final
// so we evaluate just the expression tree rooted at node N-1.
// Children of a level-l node live strictly below level l, so DFS stack
// depth <= 33. Expected tree size ~63 visits (T(l) = 2l+1).
//
// Inputs (metadata order):
//   d_in[0] values     float[L*W]
//   d_in[1] child_idx  int[(L-1)*W*2]
//   d_in[2] node_types int[(L-1)*W]
//   d_in[3] w_term     float[1]
//   d_in[4] w_plus     float[2]
//   d_in[5] w_minus    float[2]
//   d_in[6] w_final    float[1]
//   d_in[7] b_final    float[1]
// Output: float[1]

#define RN_L 32
#define RN_W 262144           // 2^18
#define RN_N (RN_L * RN_W)
#define RN_WBITS 18
#define CACHE_BITS 12
#define CACHE_SIZE (1 << CACHE_BITS)
#define MAX_DEPTH 40

__global__ void recnn_eval_kernel(const float* __restrict__ values,
                                  const int*   __restrict__ child_idx,
                                  const int*   __restrict__ node_types,
                                  const float* __restrict__ w_term,
                                  const float* __restrict__ w_plus,
                                  const float* __restrict__ w_minus,
                                  const float* __restrict__ w_final,
                                  const float* __restrict__ b_final,
                                  float*       __restrict__ out)
{
    // Direct-mapped memo cache (per-launch, initialized here -> deterministic,
    // no persistent state, graph-capture safe). Caps blowup if the actual
    // tree for this seed is heavier than expected.
    __shared__ int   c_tag[CACHE_SIZE];
    __shared__ float c_val[CACHE_SIZE];

    if (threadIdx.x != 0 || blockIdx.x != 0) return;

    #pragma unroll 8
    for (int i = 0; i < CACHE_SIZE; ++i) c_tag[i] = -1;

    const float wt  = w_term[0];
    const float wp0 = w_plus[0],  wp1 = w_plus[1];
    const float wm0 = w_minus[0], wm1 = w_minus[1];

    // Explicit DFS stack. stage: 0 = fresh, 1 = child0 done, 2 = child1 done.
    int   s_idx[MAX_DEPTH];
    int   s_stage[MAX_DEPTH];
    int   s_ch1[MAX_DEPTH];   // second child index (fetched once via int2)
    float s_c0[MAX_DEPTH];    // first child's value

    int sp = 0;
    s_idx[0] = RN_N - 1;
    s_stage[0] = 0;
    sp = 1;

    float ret = 0.0f;

    while (sp > 0) {
        const int top   = sp - 1;
        const int idx   = s_idx[top];
        const int stage = s_stage[top];

        if (stage == 0) {
            if (idx < RN_W) {                    // terminal node
                ret = values[idx] * wt;
                --sp;
                continue;
            }
            const int slot = idx & (CACHE_SIZE - 1);
            if (c_tag[slot] == idx) {            // memo hit
                ret = c_val[slot];
                --sp;
                continue;
            }
            const int lvl  = idx >> RN_WBITS;
            const int base = ((lvl - 1) << RN_WBITS) + (idx & (RN_W - 1));
            // both child indices in one 8B load (base*2 is even -> aligned)
            const int2 ch = reinterpret_cast<const int2*>(child_idx)[base];
            s_ch1[top]   = ch.y;
            s_stage[top] = 1;
            // descend into child 0
            s_idx[sp]   = ch.x;
            s_stage[sp] = 0;
            ++sp;
        } else if (stage == 1) {
            s_c0[top]    = ret;
            s_stage[top] = 2;
            // descend into child 1
            s_idx[sp]   = s_ch1[top];
            s_stage[sp] = 0;
            ++sp;
        } else {
            const int lvl  = idx >> RN_WBITS;
            const int base = ((lvl - 1) << RN_WBITS) + (idx & (RN_W - 1));
            const float x0 = s_c0[top];
            const float x1 = ret;
            const float o  = (node_types[base] == 1)
                               ? (x0 * wp0 + x1 * wp1)
                               : (x0 * wm0 + x1 * wm1);
            const int slot = idx & (CACHE_SIZE - 1);
            c_tag[slot] = idx;
            c_val[slot] = o;
            ret = o;
            --sp;
        }
    }

    out[0] = ret * w_final[0] + b_final[0];
}

extern "C" void kernel_launch(void* const* d_in, const int* in_sizes, int n_in,
                              void* d_out, int out_size)
{
    const float* values     = (const float*)d_in[0];
    const int*   child_idx  = (const int*)  d_in[1];
    const int*   node_types = (const int*)  d_in[2];
    const float* w_term     = (const float*)d_in[3];
    const float* w_plus     = (const float*)d_in[4];
    const float* w_minus    = (const float*)d_in[5];
    const float* w_final    = (const float*)d_in[6];
    const float* b_final    = (const float*)d_in[7];
    float* out = (float*)d_out;

    recnn_eval_kernel<<<1, 1>>>(values, child_idx, node_types,
                                w_term, w_plus, w_minus,
                                w_final, b_final, out);
}

// round 8
// speedup vs baseline: 3.7527x; 3.7527x over previous
#include <cuda_runtime.h>
#include <cuda_bf16.h>

// RecNN DAG evaluation — only outputs[N-1] matters, so evaluate just the
// expression tree rooted at node N-1.
//
// R7: replace single-thread DFS (serial chain = #loads ~145) with a
// warp-parallel level-synchronous BFS (serial chain = tree depth <= 31).
// Each BFS round issues all frontier nodes' loads concurrently across lanes.
// Children are appended contiguously, so "next frontier" is just a slot
// range — no queues. Evaluation runs backward over the recorded rounds,
// parallel within a round.
//
// Inputs (metadata order):
//   d_in[0] values     float[L*W]
//   d_in[1] child_idx  int[(L-1)*W*2]
//   d_in[2] node_types int[(L-1)*W]
//   d_in[3] w_term     float[1]
//   d_in[4] w_plus     float[2]
//   d_in[5] w_minus    float[2]
//   d_in[6] w_final    float[1]
//   d_in[7] b_final    float[1]
// Output: float[1]

#define RN_L 32
#define RN_W 262144           // 2^18
#define RN_N (RN_L * RN_W)
#define RN_WBITS 18
#define MAX_NODES 4096        // measured tree ~100 nodes; 40x margin
#define MAX_ROUNDS 64

__global__ void __launch_bounds__(32, 1)
recnn_bfs_kernel(const float* __restrict__ values,
                 const int*   __restrict__ child_idx,
                 const int*   __restrict__ node_types,
                 const float* __restrict__ w_term,
                 const float* __restrict__ w_plus,
                 const float* __restrict__ w_minus,
                 const float* __restrict__ w_final,
                 const float* __restrict__ b_final,
                 float*       __restrict__ out)
{
    __shared__ int   n_idx[MAX_NODES];     // node's DAG index
    __shared__ int   n_type[MAX_NODES];    // 0=terminal, 1='+', 2='-'
    __shared__ int   n_c0[MAX_NODES];      // slot of first child (c1 = c0+1)
    __shared__ __align__(8) float n_val[MAX_NODES];
    __shared__ int   r_lo[MAX_ROUNDS + 1]; // round slot boundaries

    const int lane = threadIdx.x;
    const unsigned FULL = 0xffffffffu;

    if (lane == 0) {
        n_idx[0]  = RN_N - 1;   // root
        n_type[1] = 0;          // dummy slot (keeps child pairs even-aligned)
        n_val[1]  = 0.0f;
    }
    __syncwarp();

    const float wt = __ldg(w_term);

    // ---- Phase 1: BFS expansion (chain length = tree depth) ----
    int lo = 0, hi = 1, count = 2;
    int nrounds = 0;

    while (lo < hi) {
        if (lane == 0) r_lo[nrounds] = lo;
        int newcount = count;

        for (int cb = lo; cb < hi; cb += 32) {
            const int  slot     = cb + lane;
            const bool valid    = slot < hi;
            const int  idx      = valid ? n_idx[slot] : 0;
            const bool internal = valid && (idx >= RN_W);

            int2  ch  = make_int2(0, 0);
            int   typ = 0;
            float v   = 0.0f;
            if (internal) {
                const int lvl  = idx >> RN_WBITS;
                const int base = ((lvl - 1) << RN_WBITS) + (idx & (RN_W - 1));
                ch  = __ldg(reinterpret_cast<const int2*>(child_idx) + base);
                typ = __ldg(node_types + base);
            } else if (valid) {
                v = __ldg(values + idx) * wt;   // terminal
            }

            const unsigned m    = __ballot_sync(FULL, internal);
            const int      rank = __popc(m & ((1u << lane) - 1u));
            const int      bslot = newcount + 2 * rank;

            if (internal && bslot + 1 < MAX_NODES) {
                n_type[slot] = typ;
                n_c0[slot]   = bslot;
                n_idx[bslot]     = ch.x;
                n_idx[bslot + 1] = ch.y;
            } else if (valid) {
                n_type[slot] = 0;
                n_val[slot]  = v;
            }
            newcount += 2 * __popc(m);          // uniform across lanes
        }
        __syncwarp();

        lo    = count;       // next frontier = slots allocated this round
        hi    = newcount;
        count = newcount;
        ++nrounds;
        if (nrounds >= MAX_ROUNDS) break;       // safety (never triggers)
    }
    if (lane == 0) r_lo[nrounds] = count;
    __syncwarp();

    // ---- Phase 2: bottom-up eval, round-parallel in reverse ----
    const float wp0 = __ldg(w_plus),  wp1 = __ldg(w_plus + 1);
    const float wm0 = __ldg(w_minus), wm1 = __ldg(w_minus + 1);

    for (int r = nrounds - 1; r >= 0; --r) {
        const int rlo = r_lo[r];
        const int rhi = r_lo[r + 1];
        for (int cb = rlo; cb < rhi; cb += 32) {
            const int slot = cb + lane;
            if (slot < rhi) {
                const int t = n_type[slot];
                if (t) {
                    const int c = n_c0[slot];     // even -> 8B aligned pair
                    const float2 xv = *reinterpret_cast<const float2*>(&n_val[c]);
                    n_val[slot] = (t == 1) ? (xv.x * wp0 + xv.y * wp1)
                                           : (xv.x * wm0 + xv.y * wm1);
                }
            }
        }
        __syncwarp();
    }

    if (lane == 0)
        out[0] = n_val[0] * __ldg(w_final) + __ldg(b_final);
}

extern "C" void kernel_launch(void* const* d_in, const int* in_sizes, int n_in,
                              void* d_out, int out_size)
{
    const float* values     = (const float*)d_in[0];
    const int*   child_idx  = (const int*)  d_in[1];
    const int*   node_types = (const int*)  d_in[2];
    const float* w_term     = (const float*)d_in[3];
    const float* w_plus     = (const float*)d_in[4];
    const float* w_minus    = (const float*)d_in[5];
    const float* w_final    = (const float*)d_in[6];
    const float* b_final    = (const float*)d_in[7];
    float* out = (float*)d_out;

    recnn_bfs_kernel<<<1, 32>>>(values, child_idx, node_types,
                                w_term, w_plus, w_minus,
                                w_final, b_final, out);
}

// round 9
// speedup vs baseline: 3.8493x; 1.0257x over previous
#include <cuda_runtime.h>
#include <cuda_bf16.h>

// RecNN DAG evaluation — only outputs[N-1] matters, so evaluate just the
// expression tree rooted at node N-1 (pointer chase, depth <= 31).
//
// R8: coefficient propagation. out is LINEAR in terminal values:
//   out = (sum_t coef_t * values[t]) * w_term * w_final + b_final
// where coef propagates top-down: child0 gets coef*w0, child1 gets coef*w1
// (w chosen by node type). This deletes the entire bottom-up eval phase and
// all tree-structure bookkeeping; the BFS expansion alone produces the answer.
// Serial chain = tree depth * one L2 round-trip (irreducible pointer chase).
//
// Inputs (metadata order):
//   d_in[0] values     float[L*W]
//   d_in[1] child_idx  int[(L-1)*W*2]
//   d_in[2] node_types int[(L-1)*W]
//   d_in[3] w_term     float[1]
//   d_in[4] w_plus     float[2]
//   d_in[5] w_minus    float[2]
//   d_in[6] w_final    float[1]
//   d_in[7] b_final    float[1]
// Output: float[1]

#define RN_L 32
#define RN_W 262144           // 2^18
#define RN_N (RN_L * RN_W)
#define RN_WBITS 18
#define MAX_NODES 4096        // tree ~100 nodes; huge margin

__global__ void __launch_bounds__(32, 1)
recnn_coef_kernel(const float* __restrict__ values,
                  const int*   __restrict__ child_idx,
                  const int*   __restrict__ node_types,
                  const float* __restrict__ w_term,
                  const float* __restrict__ w_plus,
                  const float* __restrict__ w_minus,
                  const float* __restrict__ w_final,
                  const float* __restrict__ b_final,
                  float*       __restrict__ out)
{
    // frontier: packed (node_idx, coef bits). Append-only; each round reads
    // [lo,hi) and appends children at wpos. Even slots -> int4 stores are
    // 16B aligned.
    __shared__ __align__(16) int2 fr[MAX_NODES];

    const int lane = threadIdx.x;
    const unsigned FULL = 0xffffffffu;
    const unsigned lt_mask = (1u << lane) - 1u;

    const float wp0 = __ldg(w_plus),  wp1 = __ldg(w_plus + 1);
    const float wm0 = __ldg(w_minus), wm1 = __ldg(w_minus + 1);

    float acc = 0.0f;

    // ---- round 0: root (always internal, level 31) handled in registers ----
    if (lane == 0) {
        const int idx  = RN_N - 1;
        const int lvl  = idx >> RN_WBITS;
        const int base = ((lvl - 1) << RN_WBITS) + (idx & (RN_W - 1));
        const int2 ch  = __ldg(reinterpret_cast<const int2*>(child_idx) + base);
        const int  typ = __ldg(node_types + base);
        const float w0 = (typ == 1) ? wp0 : wm0;
        const float w1 = (typ == 1) ? wp1 : wm1;
        *reinterpret_cast<int4*>(&fr[0]) =
            make_int4(ch.x, __float_as_int(w0), ch.y, __float_as_int(w1));
    }
    __syncwarp();

    int lo = 0, hi = 2, wpos = 2;

    while (lo < hi) {
        for (int cb = lo; cb < hi; cb += 32) {
            const int  slot = cb + lane;
            const bool v    = slot < hi;
            const int2 f    = v ? fr[slot] : make_int2(0, 0);
            const int   idx  = f.x;
            const float coef = __int_as_float(f.y);
            const bool internal = v && (idx >= RN_W);

            int2 ch  = make_int2(0, 0);
            int  typ = 1;
            if (internal) {
                const int lvl  = idx >> RN_WBITS;
                const int base = ((lvl - 1) << RN_WBITS) + (idx & (RN_W - 1));
                ch  = __ldg(reinterpret_cast<const int2*>(child_idx) + base);
                typ = __ldg(node_types + base);
            } else if (v) {
                acc += coef * __ldg(values + idx);   // terminal
            }

            const unsigned m    = __ballot_sync(FULL, internal);
            const int      rank = __popc(m & lt_mask);
            const int      b    = wpos + 2 * rank;
            if (internal && (b + 1) < MAX_NODES) {
                const float w0 = (typ == 1) ? wp0 : wm0;
                const float w1 = (typ == 1) ? wp1 : wm1;
                *reinterpret_cast<int4*>(&fr[b]) =
                    make_int4(ch.x, __float_as_int(coef * w0),
                              ch.y, __float_as_int(coef * w1));
            }
            wpos += 2 * __popc(m);                   // uniform across lanes
        }
        __syncwarp();
        lo = hi;
        hi = wpos;
    }

    // deterministic warp reduction of the terminal accumulator
    #pragma unroll
    for (int o = 16; o > 0; o >>= 1)
        acc += __shfl_xor_sync(FULL, acc, o);

    if (lane == 0)
        out[0] = acc * __ldg(w_term) * __ldg(w_final) + __ldg(b_final);
}

extern "C" void kernel_launch(void* const* d_in, const int* in_sizes, int n_in,
                              void* d_out, int out_size)
{
    const float* values     = (const float*)d_in[0];
    const int*   child_idx  = (const int*)  d_in[1];
    const int*   node_types = (const int*)  d_in[2];
    const float* w_term     = (const float*)d_in[3];
    const float* w_plus     = (const float*)d_in[4];
    const float* w_minus    = (const float*)d_in[5];
    const float* w_final    = (const float*)d_in[6];
    const float* b_final    = (const float*)d_in[7];
    float* out = (float*)d_out;

    recnn_coef_kernel<<<1, 32>>>(values, child_idx, node_types,
                                 w_term, w_plus, w_minus,
                                 w_final, b_final, out);
}